// round 9
// baseline (speedup 1.0000x reference)
#include <cuda_runtime.h>

// KAN 3x3 convolution, single channel, uniform cubic B-spline (G=5, s=3, h=0.4).
//
// Truncated-power reformulation: for x in [0,1) each tap's spline response is a C2
// piecewise cubic with knots at x=0.2, 0.6, hence EXACTLY
//   g_p(x) = C0+C1 x+C2 x^2+C3 x^3 + alpha*relu(x-0.2)^3 + beta*relu(x-0.6)^3 + silu(x)*bw_p
// (alpha/beta = jumps of the cubic coefficient across the knots).
// A tiny pre-kernel computes {C0..C3, alpha, beta, bw} per tap (fp64 transform) into a
// __device__ buffer; a D2D memcpy stages it into __constant__ so the main kernel reads
// weights over the uniform-register/const path (low GPR count).
// Phase 1: per input pixel, 6 FMA per tap + ~8 shared ops; planes stored SHIFTED by -b.
// Phase 2: out(h, w..w+3) = sum over 9 planes of one aligned float4 (LDS.128 + f32x2 adds).

#define TW 64
#define TH 16
#define IW (TW + 2)          // 66
#define IH (TH + 2)          // 18
#define GPAD 68              // padded row stride (floats); 272B rows keep 16B alignment
#define PS (IH * GPAD)       // plane stride = 1224 floats
#define NPIX (IH * IW)       // 1188
#define NTHREADS 256
#define NITER ((NPIX + NTHREADS - 1) / NTHREADS)   // 5
#define WIDTH 256
#define HO 254
#define WO 254

typedef unsigned long long ull;

#define UNPACK2(lo, hi, s) asm("mov.b64 {%0, %1}, %2;" : "=f"(lo), "=f"(hi) : "l"(s))
#define ADD2(d, a, b)      asm("add.rn.f32x2 %0, %1, %2;" : "=l"(d) : "l"(a), "l"(b))

__constant__ float cCF[72];      // [9][8]: C0,C1,C2,C3, alpha, beta, bw, pad
__device__   float dCF[72];      // staging buffer written by prep_kernel

// ---- pre-kernel: weight -> truncated-power coefficients (fp64 for the transform) ----
__global__ void prep_kernel(const float* __restrict__ BWg,
                            const float* __restrict__ SWg)
{
    int p = threadIdx.x;
    if (p >= 9) return;

    double w[8];
#pragma unroll
    for (int k = 0; k < 8; ++k) w[k] = (double)SWg[p * 8 + k];

    const double q  = 2.5;        // u = q*x + d,  d = 0.5 - l
    const double q2 = q * q, q3 = q2 * q;

    double a3piece[3], C0 = 0, C1 = 0, C2 = 0, C3 = 0;
#pragma unroll
    for (int l = 0; l < 3; ++l) {
        double v0 = w[2 + l], v1 = w[3 + l], v2 = w[4 + l], v3 = w[5 + l];
        // cubic in u: A0 + A1 u + A2 u^2 + A3 u^3 (uniform cubic B-spline matrix)
        double A0 = (v0 + 4.0 * v1 + v2) * (1.0 / 6.0);
        double A1 = 0.5 * (v2 - v0);
        double A2 = 0.5 * (v0 - 2.0 * v1 + v2);
        double A3 = (-v0 + 3.0 * v1 - 3.0 * v2 + v3) * (1.0 / 6.0);
        double d  = 0.5 - (double)l;
        a3piece[l] = A3 * q3;
        if (l == 0) {
            C3 = A3 * q3;
            C2 = q2 * (A2 + 3.0 * A3 * d);
            C1 = q  * (A1 + d * (2.0 * A2 + 3.0 * A3 * d));
            C0 = A0 + d * (A1 + d * (A2 + d * A3));
        }
    }

    dCF[p * 8 + 0] = (float)C0;
    dCF[p * 8 + 1] = (float)C1;
    dCF[p * 8 + 2] = (float)C2;
    dCF[p * 8 + 3] = (float)C3;
    dCF[p * 8 + 4] = (float)(a3piece[1] - a3piece[0]);   // alpha
    dCF[p * 8 + 5] = (float)(a3piece[2] - a3piece[1]);   // beta
    dCF[p * 8 + 6] = BWg[p];
    dCF[p * 8 + 7] = 0.0f;
}

// ---- main kernel ----
__global__ void __launch_bounds__(NTHREADS, 5)
kan_conv_kernel(const float* __restrict__ X,
                float* __restrict__ OUT)
{
    // +8 floats: shifted halo writes (col' up to 69 on the last plane/row) stay in-bounds.
    __shared__ __align__(16) float gs[9 * PS + 8];   // 44096 B

    const int tid = threadIdx.x;
    const int w0  = blockIdx.x * TW;
    const int h0  = blockIdx.y * TH;
    const float* Xi = X + (size_t)blockIdx.z * (WIDTH * WIDTH);

    // ---------------- Phase 1 ----------------
    // front-batched global loads (MLP = NITER) + precomputed smem base offsets
    float xv[NITER];
    int   sb[NITER];
#pragma unroll
    for (int it = 0; it < NITER; ++it) {
        int i  = tid + it * NTHREADS;
        int ii = (i < NPIX) ? i : 0;
        int r  = ii / IW;
        int c  = ii - r * IW;
        sb[it] = r * GPAD + c + 4;               // plane p writes sb - (p%3)
        int gr = min(h0 + r, WIDTH - 1);
        int gc = min(w0 + c, WIDTH - 1);
        xv[it] = __ldg(Xi + gr * WIDTH + gc);
    }

#pragma unroll
    for (int it = 0; it < NITER; ++it) {
        float x = xv[it];

        // shared per-pixel features
        float t1 = fmaxf(x - 0.2f, 0.0f);
        float t2 = fmaxf(x - 0.6f, 0.0f);
        float r1 = t1 * t1 * t1;                 // relu(x-0.2)^3
        float r2 = t2 * t2 * t2;                 // relu(x-0.6)^3

        // silu(x) = x / (1 + e^{-x})
        float e = __expf(-x);
        float s = x * __fdividef(1.0f, 1.0f + e);

        if (tid + it * NTHREADS < NPIX) {
            float* base = gs + sb[it];
#pragma unroll
            for (int p = 0; p < 9; ++p) {
                float g = fmaf(cCF[p * 8 + 3], x, cCF[p * 8 + 2]);   // Horner
                g = fmaf(g, x, cCF[p * 8 + 1]);
                g = fmaf(g, x, cCF[p * 8 + 0]);
                g = fmaf(cCF[p * 8 + 4], r1, g);                     // alpha knot
                g = fmaf(cCF[p * 8 + 5], r2, g);                     // beta knot
                g = fmaf(cCF[p * 8 + 6], s,  g);                     // silu * bw
                base[p * PS - (p % 3)] = g;
            }
        }
    }
    __syncthreads();

    // ---------------- Phase 2: 4 outputs/thread, 9 aligned 16B smem loads ----
    const int lw4 = (tid & 15) * 4;
    const int lh  = tid >> 4;
    const int h   = h0 + lh;

    if (h < HO) {
        const char* rbase = (const char*)(gs + lh * GPAD + lw4 + 4);
        ulonglong2 v0 = *(const ulonglong2*)(rbase);
        ull alo = v0.x, ahi = v0.y;
#pragma unroll
        for (int a = 0; a < 3; ++a)
#pragma unroll
            for (int b = 0; b < 3; ++b) {
                if (a == 0 && b == 0) continue;
                ulonglong2 v = *(const ulonglong2*)(rbase +
                        ((a * 3 + b) * PS + a * GPAD) * sizeof(float));
                ADD2(alo, alo, v.x);
                ADD2(ahi, ahi, v.y);
            }

        const int w = w0 + lw4;
        float* op = OUT + (size_t)blockIdx.z * (HO * WO) + (size_t)h * WO + w;
        if (w + 3 < WO) {
            *(ull*)(op)     = alo;
            *(ull*)(op + 2) = ahi;
        } else {
            float f0, f1, f2, f3;
            UNPACK2(f0, f1, alo);
            UNPACK2(f2, f3, ahi);
            if (w     < WO) op[0] = f0;
            if (w + 1 < WO) op[1] = f1;
            if (w + 2 < WO) op[2] = f2;
            if (w + 3 < WO) op[3] = f3;
        }
    }
}

extern "C" void kernel_launch(void* const* d_in, const int* in_sizes, int n_in,
                              void* d_out, int out_size)
{
    const float* x  = (const float*)d_in[0];
    const float* bw = (const float*)d_in[1];
    const float* sw = (const float*)d_in[2];
    float* out = (float*)d_out;

    // 1) transform weights -> truncated-power coefficients (device buffer)
    prep_kernel<<<1, 32>>>(bw, sw);

    // 2) stage into __constant__ (D2D memcpy node; graph-capturable)
    void* dcf_ptr = nullptr;
    cudaGetSymbolAddress(&dcf_ptr, dCF);
    cudaMemcpyToSymbolAsync(cCF, dcf_ptr, 72 * sizeof(float), 0,
                            cudaMemcpyDeviceToDevice, 0);

    // 3) main kernel
    int batch = in_sizes[0] / (WIDTH * WIDTH);   // 32
    dim3 grid((WO + TW - 1) / TW, (HO + TH - 1) / TH, batch);
    kan_conv_kernel<<<grid, NTHREADS>>>(x, out);
}

// round 10
// speedup vs baseline: 1.1235x; 1.1235x over previous
#include <cuda_runtime.h>

// KAN 3x3 convolution, single channel, uniform cubic B-spline (G=5, s=3, h=0.4).
// x in [0,1) -> knot interval j in {5,6,7}; 4 active bases placed in 6 slots (c=2..7).
// Phase 1: per input pixel g_p = silu(x)*bw[p] + sum_s m_s*sw[p][s+2], 9 taps p=(a,b);
//          spline weights in __constant__ (LDCU -> uniform regs), base weights via
//          __ldg (9 GPRs). Planes stored SHIFTED by -b so phase 2 reads one column.
// Phase 2: out(h, w), 2 outputs/thread: 9 aligned LDS.64 + 8 packed f32x2 adds.
// Small 32x16 tile + low reg target -> 6 blocks/SM (75% occupancy).

#define TW 32
#define TH 16
#define IW (TW + 2)          // 34
#define IH (TH + 2)          // 18
#define GPAD 36              // padded row stride (floats); 144B rows = 16B multiple
#define PS (IH * GPAD)       // plane stride = 648 floats
#define NPIX (IH * IW)       // 612
#define NTHREADS 256
#define NITER ((NPIX + NTHREADS - 1) / NTHREADS)   // 3
#define WIDTH 256
#define HO 254
#define WO 254

typedef unsigned long long ull;

#define UNPACK2(lo, hi, s) asm("mov.b64 {%0, %1}, %2;" : "=f"(lo), "=f"(hi) : "l"(s))
#define ADD2(d, a, b)      asm("add.rn.f32x2 %0, %1, %2;" : "=l"(d) : "l"(a), "l"(b))

__constant__ float cSW[72];    // spline weights, [9][8]

__global__ void __launch_bounds__(NTHREADS, 6)
kan_conv_kernel(const float* __restrict__ X,
                const float* __restrict__ BWg,
                float* __restrict__ OUT)
{
    // plane p=(a,b) stores input col c at col' = c + 2 - b  (range 0..35, in-bounds)
    __shared__ __align__(16) float gs[9 * PS];   // 23328 B

    const int tid = threadIdx.x;
    const int w0  = blockIdx.x * TW;
    const int h0  = blockIdx.y * TH;
    const float* Xi = X + (size_t)blockIdx.z * (WIDTH * WIDTH);

    // base weights -> 9 regs (block-uniform broadcast hits)
    float BW[9];
#pragma unroll
    for (int p = 0; p < 9; ++p) BW[p] = __ldg(BWg + p);

    // ---------------- Phase 1 ----------------
    // front-batched global loads (MLP = NITER)
    float xv[NITER];
#pragma unroll
    for (int it = 0; it < NITER; ++it) {
        int i  = tid + it * NTHREADS;
        int ii = (i < NPIX) ? i : 0;
        int r  = ii / IW;
        int c  = ii - r * IW;
        int gr = min(h0 + r, WIDTH - 1);
        int gc = min(w0 + c, WIDTH - 1);
        xv[it] = __ldg(Xi + gr * WIDTH + gc);
    }

#pragma unroll
    for (int it = 0; it < NITER; ++it) {
        int i  = tid + it * NTHREADS;
        int ii = (i < NPIX) ? i : 0;
        int r  = ii / IW;
        int c  = ii - r * IW;
        float x = xv[it];

        float y  = fmaf(x, 2.5f, 5.5f);          // (x + 2.2) / 0.4  -> [5.5, 8.0)
        float jf = floorf(y);                    // in {5,6,7}
        float u  = y - jf;

        const float c16 = 0.16666666666666666f;
        float omu = 1.0f - u;
        float u2  = u * u;
        float n0 = omu * omu * omu * c16;
        float n3 = u2 * u * c16;
        float n1 = fmaf(u2, fmaf(0.5f, u, -1.0f), 0.6666666666666666f);
        float n2 = 1.0f - n0 - n1 - n3;          // partition of unity

        bool j0 = (jf == 5.0f), j1 = (jf == 6.0f);
        float m0 = j0 ? n0 : 0.0f;
        float m1 = j0 ? n1 : (j1 ? n0 : 0.0f);
        float m2 = j0 ? n2 : (j1 ? n1 : n0);
        float m3 = j0 ? n3 : (j1 ? n2 : n1);
        float m4 = j0 ? 0.0f : (j1 ? n3 : n2);
        float m5 = (j0 || j1) ? 0.0f : n3;

        // silu(x) = x / (1 + e^{-x})
        float e = __expf(-x);
        float s = x * __fdividef(1.0f, 1.0f + e);

        if (i < NPIX) {
            float* base = gs + r * GPAD + c + 2;
#pragma unroll
            for (int p = 0; p < 9; ++p) {
                float g = s * BW[p];
                g = fmaf(m0, cSW[p * 8 + 2], g);
                g = fmaf(m1, cSW[p * 8 + 3], g);
                g = fmaf(m2, cSW[p * 8 + 4], g);
                g = fmaf(m3, cSW[p * 8 + 5], g);
                g = fmaf(m4, cSW[p * 8 + 6], g);
                g = fmaf(m5, cSW[p * 8 + 7], g);
                base[p * PS - (p % 3)] = g;
            }
        }
    }
    __syncthreads();

    // ---------------- Phase 2: 2 outputs/thread, 9 aligned 8B smem loads ----
    const int lw2 = (tid & 15) * 2;              // 0..30
    const int lh  = tid >> 4;                    // 0..15
    const int h   = h0 + lh;

    if (h < HO) {
        const char* rbase = (const char*)(gs + lh * GPAD + lw2 + 2);
        ull acc = *(const ull*)(rbase);          // plane 0, a=0
#pragma unroll
        for (int a = 0; a < 3; ++a)
#pragma unroll
            for (int b = 0; b < 3; ++b) {
                if (a == 0 && b == 0) continue;
                ull v = *(const ull*)(rbase +
                        ((a * 3 + b) * PS + a * GPAD) * sizeof(float));
                ADD2(acc, acc, v);
            }

        const int w = w0 + lw2;
        float* op = OUT + (size_t)blockIdx.z * (HO * WO) + (size_t)h * WO + w;
        if (w + 1 < WO) {
            *(ull*)op = acc;                     // 8B-aligned (h*254 + w even)
        } else if (w < WO) {
            float f0, f1;
            UNPACK2(f0, f1, acc);
            op[0] = f0;
        }
    }
}

extern "C" void kernel_launch(void* const* d_in, const int* in_sizes, int n_in,
                              void* d_out, int out_size)
{
    const float* x  = (const float*)d_in[0];
    const float* bw = (const float*)d_in[1];
    float* out = (float*)d_out;

    // Stage spline weights into __constant__ (one D2D async copy, graph-capturable).
    cudaMemcpyToSymbolAsync(cSW, d_in[2], 72 * sizeof(float), 0,
                            cudaMemcpyDeviceToDevice, 0);

    int batch = in_sizes[0] / (WIDTH * WIDTH);   // 32
    dim3 grid((WO + TW - 1) / TW, (HO + TH - 1) / TH, batch);
    kan_conv_kernel<<<grid, NTHREADS>>>(x, bw, out);
}